// round 4
// baseline (speedup 1.0000x reference)
#include <cuda_runtime.h>
#include <math.h>

#define SEQ   2048
#define DM    1024
#define NH    16
#define DEP   64
#define BATCHN 4
#define MROWS (BATCHN*SEQ)   /* 8192 */
#define BHN   (BATCHN*NH)    /* 64   */

// Scratch (allocation-free rule: __device__ globals)
__device__ float g_q[(size_t)BHN*SEQ*DEP];
__device__ float g_k[(size_t)BHN*SEQ*DEP];
__device__ float g_v[(size_t)BHN*SEQ*DEP];
__device__ float g_multi[(size_t)MROWS*DM];

// ---------------------------------------------------------------------------
// SGEMM: C[M=8192, N=1024] = A[M,K=1024] * W + bias
// mode 0: W is [K,N] row-major (Wo), C stored row-major [M,N]
// mode 1: W is [H][K][64] (per-head stacked), C stored as [BH][S][64]
// 128x128 block tile, BK=8, 256 threads, 8x8 per-thread micro-tile.
// ---------------------------------------------------------------------------
__global__ __launch_bounds__(256) void sgemm_kernel(
    const float* __restrict__ A, const float* __restrict__ W,
    const float* __restrict__ bias, float* __restrict__ C, int mode)
{
    const int K = DM, N = DM;
    __shared__ float As[8][128];
    __shared__ float Bs[8][128];

    const int tid  = threadIdx.x;
    const int m0   = blockIdx.y * 128;
    const int n0   = blockIdx.x * 128;
    const int arow = tid >> 1;
    const int acol = (tid & 1) << 2;
    const int brow = tid >> 5;
    const int bn   = (tid & 31) << 2;
    const int ry   = tid >> 4;
    const int tx   = tid & 15;

    float acc[8][8];
#pragma unroll
    for (int i = 0; i < 8; i++)
#pragma unroll
        for (int j = 0; j < 8; j++) acc[i][j] = 0.f;

    const float* aptr = A + (size_t)(m0 + arow) * K + acol;

    for (int kt = 0; kt < K; kt += 8) {
        float4 av = *(const float4*)(aptr + kt);
        const float* bp;
        if (mode == 0) {
            bp = W + (size_t)(kt + brow) * N + n0 + bn;
        } else {
            int n = n0 + bn;
            bp = W + (size_t)((n >> 6) * K + kt + brow) * DEP + (n & 63);
        }
        float4 bv = *(const float4*)bp;

        As[acol + 0][arow] = av.x;
        As[acol + 1][arow] = av.y;
        As[acol + 2][arow] = av.z;
        As[acol + 3][arow] = av.w;
        *(float4*)&Bs[brow][bn] = bv;
        __syncthreads();

#pragma unroll
        for (int kk = 0; kk < 8; kk++) {
            float4 a0 = *(const float4*)&As[kk][ry << 2];
            float4 a1 = *(const float4*)&As[kk][64 + (ry << 2)];
            float4 b0 = *(const float4*)&Bs[kk][tx << 2];
            float4 b1 = *(const float4*)&Bs[kk][64 + (tx << 2)];
            float a[8] = {a0.x, a0.y, a0.z, a0.w, a1.x, a1.y, a1.z, a1.w};
            float b[8] = {b0.x, b0.y, b0.z, b0.w, b1.x, b1.y, b1.z, b1.w};
#pragma unroll
            for (int i = 0; i < 8; i++)
#pragma unroll
                for (int j = 0; j < 8; j++)
                    acc[i][j] = fmaf(a[i], b[j], acc[i][j]);
        }
        __syncthreads();
    }

    // Epilogue: bias add + store (mode-dependent layout)
#pragma unroll
    for (int i = 0; i < 8; i++) {
        int r = m0 + ((i < 4) ? ((ry << 2) + i) : (64 + (ry << 2) + i - 4));
#pragma unroll
        for (int jg = 0; jg < 2; jg++) {
            int n = n0 + jg * 64 + (tx << 2);
            float4 val;
            val.x = acc[i][jg * 4 + 0] + bias[n + 0];
            val.y = acc[i][jg * 4 + 1] + bias[n + 1];
            val.z = acc[i][jg * 4 + 2] + bias[n + 2];
            val.w = acc[i][jg * 4 + 3] + bias[n + 3];
            if (mode == 0) {
                *(float4*)&C[(size_t)r * N + n] = val;
            } else {
                int b = r >> 11, s = r & 2047;
                int h = n >> 6,  e = n & 63;
                *(float4*)&C[(((size_t)(b * NH + h)) * SEQ + s) * DEP + e] = val;
            }
        }
    }
}

// ---------------------------------------------------------------------------
// Flash-style attention (fp32, online softmax).
// grid = (SEQ/16, BH); block = 512 (16 warps). One warp owns one query row.
// Key/value tiles of 64 rows shared across the block. multi stored as
// [B, S, H*64] (concat-heads layout) so the output projection is a plain GEMM.
// ---------------------------------------------------------------------------
#define AT_ROWS 16
#define AT_TK   64

__global__ __launch_bounds__(512) void attn_kernel(
    const float* __restrict__ q, const float* __restrict__ k,
    const float* __restrict__ v, float* __restrict__ multi)
{
    __shared__ float Ks[AT_TK][65];   // stride 65: conflict-free row reads
    __shared__ float Vs[AT_TK][65];
    __shared__ float Qs[AT_ROWS][64];
    __shared__ float Ps[AT_ROWS][64];

    const int tid  = threadIdx.x;
    const int warp = tid >> 5;
    const int lane = tid & 31;
    const int bh   = blockIdx.y;
    const int qrow = blockIdx.x * AT_ROWS + warp;

    const float* qp = q + ((size_t)bh * SEQ + qrow) * DEP;
    Qs[warp][lane]      = qp[lane];
    Qs[warp][lane + 32] = qp[lane + 32];

    float mval = -1e30f, l = 0.f, o0 = 0.f, o1 = 0.f;
    const float scale = 0.125f;  // 1/sqrt(64)
    const float* kbase = k + (size_t)bh * SEQ * DEP;
    const float* vbase = v + (size_t)bh * SEQ * DEP;

    for (int t0 = 0; t0 < SEQ; t0 += AT_TK) {
        __syncthreads();
        // Cooperative tile load: coalesced global reads, conflict-free STS
        for (int i = tid; i < AT_TK * DEP; i += 512) {
            int row = i >> 6, col = i & 63;
            Ks[row][col] = kbase[(size_t)(t0 + row) * DEP + col];
            Vs[row][col] = vbase[(size_t)(t0 + row) * DEP + col];
        }
        __syncthreads();

        // scores: lane handles keys (lane) and (lane+32)
        float s0 = 0.f, s1 = 0.f;
#pragma unroll
        for (int d = 0; d < 64; d++) {
            float qd = Qs[warp][d];
            s0 = fmaf(qd, Ks[lane][d], s0);
            s1 = fmaf(qd, Ks[lane + 32][d], s1);
        }
        s0 *= scale; s1 *= scale;

        float mt = fmaxf(s0, s1);
#pragma unroll
        for (int off = 16; off > 0; off >>= 1)
            mt = fmaxf(mt, __shfl_xor_sync(0xffffffffu, mt, off));
        float mnew = fmaxf(mval, mt);
        float corr = __expf(mval - mnew);
        float p0 = __expf(s0 - mnew);
        float p1 = __expf(s1 - mnew);
        float ps = p0 + p1;
#pragma unroll
        for (int off = 16; off > 0; off >>= 1)
            ps += __shfl_xor_sync(0xffffffffu, ps, off);
        l = l * corr + ps;
        o0 *= corr; o1 *= corr;

        Ps[warp][lane]      = p0;
        Ps[warp][lane + 32] = p1;
        __syncwarp();

#pragma unroll
        for (int j = 0; j < AT_TK; j++) {
            float pj = Ps[warp][j];
            o0 = fmaf(pj, Vs[j][lane], o0);
            o1 = fmaf(pj, Vs[j][lane + 32], o1);
        }
        mval = mnew;
    }

    float inv = 1.f / l;
    int b = bh >> 4, h = bh & 15;
    float* op = multi + ((size_t)(b * SEQ) + qrow) * DM + h * DEP;
    op[lane]      = o0 * inv;
    op[lane + 32] = o1 * inv;
}

// ---------------------------------------------------------------------------
// Launch: 3 QKV GEMMs -> attention -> output GEMM. All graph-capturable.
// ---------------------------------------------------------------------------
extern "C" void kernel_launch(void* const* d_in, const int* in_sizes, int n_in,
                              void* d_out, int out_size)
{
    const float* x  = (const float*)d_in[0];
    const float* Wq = (const float*)d_in[1];
    const float* bq = (const float*)d_in[2];
    const float* Wk = (const float*)d_in[3];
    const float* bk = (const float*)d_in[4];
    const float* Wv = (const float*)d_in[5];
    const float* bv = (const float*)d_in[6];
    const float* Wo = (const float*)d_in[7];
    const float* bo = (const float*)d_in[8];
    float* out = (float*)d_out;

    float *qb, *kb, *vb, *mb;
    cudaGetSymbolAddress((void**)&qb, g_q);
    cudaGetSymbolAddress((void**)&kb, g_k);
    cudaGetSymbolAddress((void**)&vb, g_v);
    cudaGetSymbolAddress((void**)&mb, g_multi);

    dim3 gg(DM / 128, MROWS / 128);   // (8, 64)
    sgemm_kernel<<<gg, 256>>>(x, Wq, bq, qb, 1);
    sgemm_kernel<<<gg, 256>>>(x, Wk, bk, kb, 1);
    sgemm_kernel<<<gg, 256>>>(x, Wv, bv, vb, 1);

    dim3 ga(SEQ / AT_ROWS, BHN);      // (128, 64)
    attn_kernel<<<ga, 512>>>(qb, kb, vb, mb);

    sgemm_kernel<<<gg, 256>>>(mb, Wo, bo, out, 0);
}

// round 5
// speedup vs baseline: 3.8765x; 3.8765x over previous
#include <cuda_runtime.h>
#include <math.h>
#include <stdint.h>

#define SEQ    2048
#define DM     1024
#define NH     16
#define DEP    64
#define BATCHN 4
#define MROWS  (BATCHN*SEQ)   /* 8192 */
#define BHN    (BATCHN*NH)    /* 64   */

// Scratch (allocation-free rule: __device__ globals)
__device__ float g_q[(size_t)BHN*SEQ*DEP];
__device__ float g_k[(size_t)BHN*SEQ*DEP];
__device__ float g_v[(size_t)BHN*SEQ*DEP];
__device__ float g_multi[(size_t)MROWS*DM];

// ---------------------------------------------------------------------------
// tf32 helpers
// ---------------------------------------------------------------------------
__device__ __forceinline__ uint32_t f2tf(float x) {
    uint32_t u;
    asm("cvt.rna.tf32.f32 %0, %1;" : "=r"(u) : "f"(x));
    return u;
}

// D += A(16x8, row) * B(8x8, col)  tf32 -> f32
__device__ __forceinline__ void mma8(float* c,
    uint32_t a0, uint32_t a1, uint32_t a2, uint32_t a3,
    uint32_t b0, uint32_t b1)
{
    asm volatile(
        "mma.sync.aligned.m16n8k8.row.col.f32.tf32.tf32.f32 "
        "{%0,%1,%2,%3}, {%4,%5,%6,%7}, {%8,%9}, {%0,%1,%2,%3};"
        : "+f"(c[0]), "+f"(c[1]), "+f"(c[2]), "+f"(c[3])
        : "r"(a0), "r"(a1), "r"(a2), "r"(a3), "r"(b0), "r"(b1));
}

// ---------------------------------------------------------------------------
// tf32 tensor-core GEMM: C[8192,1024] = A[8192,1024] * W[1024,1024] + bias
// mode 0: W row-major [K,N] (Wo), C row-major [M,N]
// mode 1: W = [H][K][64] stacked, C stored as [BH][S][64]
// 128x128 block, BK=32, 256 threads (8 warps of 64x32), m16n8k8.
// Smem strides: As stride 36 (4g+t conflict-free), Bs stride 136 (8t+g c.f.)
// ---------------------------------------------------------------------------
#define AS_ST 36
#define BS_ST 136

__global__ __launch_bounds__(256) void gemm_tf32(
    const float* __restrict__ A, const float* __restrict__ W,
    const float* __restrict__ bias, float* __restrict__ C, int mode)
{
    __shared__ uint32_t As[128 * AS_ST];
    __shared__ uint32_t Bs[32 * BS_ST];

    const int tid  = threadIdx.x;
    const int m0   = blockIdx.y * 128;
    const int n0   = blockIdx.x * 128;
    const int warp = tid >> 5;
    const int lane = tid & 31;
    const int g    = lane >> 2;
    const int t    = lane & 3;
    const int wm   = (warp >> 2) * 64;   // 0 or 64
    const int wn   = (warp & 3) * 32;    // 0,32,64,96

    float acc[4][4][4];
#pragma unroll
    for (int mi = 0; mi < 4; mi++)
#pragma unroll
        for (int ni = 0; ni < 4; ni++)
#pragma unroll
            for (int r = 0; r < 4; r++) acc[mi][ni][r] = 0.f;

    for (int kt = 0; kt < DM; kt += 32) {
        // ---- load A tile 128x32 (1024 float4s, 4 per thread) ----
#pragma unroll
        for (int p = 0; p < 4; p++) {
            int f4  = p * 256 + tid;
            int row = f4 >> 3;
            int c4  = (f4 & 7) << 2;
            float4 v = *(const float4*)(A + (size_t)(m0 + row) * DM + kt + c4);
            uint32_t* dst = &As[row * AS_ST + c4];
            dst[0] = f2tf(v.x); dst[1] = f2tf(v.y);
            dst[2] = f2tf(v.z); dst[3] = f2tf(v.w);
        }
        // ---- load B tile 32x128 ----
#pragma unroll
        for (int p = 0; p < 4; p++) {
            int f4  = p * 256 + tid;
            int row = f4 >> 5;
            int c4  = (f4 & 31) << 2;
            const float* src;
            if (mode == 0) {
                src = W + (size_t)(kt + row) * DM + n0 + c4;
            } else {
                int n = n0 + c4;
                src = W + (size_t)(n >> 6) * (DM * DEP) + (size_t)(kt + row) * DEP + (n & 63);
            }
            float4 v = *(const float4*)src;
            uint32_t* dst = &Bs[row * BS_ST + c4];
            dst[0] = f2tf(v.x); dst[1] = f2tf(v.y);
            dst[2] = f2tf(v.z); dst[3] = f2tf(v.w);
        }
        __syncthreads();

#pragma unroll
        for (int kk = 0; kk < 4; kk++) {
            const int k = kk * 8;
            uint32_t a[4][4];
#pragma unroll
            for (int mi = 0; mi < 4; mi++) {
                int r0 = wm + mi * 16 + g;
                a[mi][0] = As[(r0)     * AS_ST + k + t];
                a[mi][1] = As[(r0 + 8) * AS_ST + k + t];
                a[mi][2] = As[(r0)     * AS_ST + k + t + 4];
                a[mi][3] = As[(r0 + 8) * AS_ST + k + t + 4];
            }
#pragma unroll
            for (int ni = 0; ni < 4; ni++) {
                uint32_t b0 = Bs[(k + t)     * BS_ST + wn + ni * 8 + g];
                uint32_t b1 = Bs[(k + t + 4) * BS_ST + wn + ni * 8 + g];
#pragma unroll
                for (int mi = 0; mi < 4; mi++)
                    mma8(acc[mi][ni], a[mi][0], a[mi][1], a[mi][2], a[mi][3], b0, b1);
            }
        }
        __syncthreads();
    }

    // ---- epilogue: bias + store ----
#pragma unroll
    for (int mi = 0; mi < 4; mi++) {
        int row0 = m0 + wm + mi * 16 + g;
#pragma unroll
        for (int ni = 0; ni < 4; ni++) {
            int col = n0 + wn + ni * 8 + 2 * t;
            float bx = bias[col], by = bias[col + 1];
#pragma unroll
            for (int h = 0; h < 2; h++) {          // h=0: row g, h=1: row g+8
                int row = row0 + h * 8;
                float2 val;
                val.x = acc[mi][ni][h * 2 + 0] + bx;
                val.y = acc[mi][ni][h * 2 + 1] + by;
                if (mode == 0) {
                    *(float2*)&C[(size_t)row * DM + col] = val;
                } else {
                    int b = row >> 11, s = row & 2047;
                    int hh = col >> 6, e = col & 63;
                    *(float2*)&C[(((size_t)(b * NH + hh)) * SEQ + s) * DEP + e] = val;
                }
            }
        }
    }
}

// ---------------------------------------------------------------------------
// Tensor-core flash attention (tf32 MMA, fp32 online softmax).
// Block = 128 threads (4 warps), each warp owns 16 query rows.
// Q tile 64x64 per block, key tiles of 64. grid = (SEQ/64, BH).
// Smem (dynamic): Qs/Ks/Ps stride 68 (4g+t c.f.), Vs stride 72 (8t+g c.f.)
// ---------------------------------------------------------------------------
#define Q_ST 68
#define V_ST 72
#define OFF_Q 0
#define OFF_K (64 * Q_ST)          /* 4352  */
#define OFF_P (2 * 64 * Q_ST)      /* 8704  */
#define OFF_V (3 * 64 * Q_ST)      /* 13056 */
#define ATT_SMEM_WORDS (3 * 64 * Q_ST + 64 * V_ST)  /* 17664 */

__global__ __launch_bounds__(128) void attn_tc(
    const float* __restrict__ q, const float* __restrict__ k,
    const float* __restrict__ v, float* __restrict__ multi)
{
    extern __shared__ uint32_t sm[];
    uint32_t* Qs = sm + OFF_Q;
    uint32_t* Ks = sm + OFF_K;
    uint32_t* Ps = sm + OFF_P;
    uint32_t* Vs = sm + OFF_V;

    const int tid  = threadIdx.x;
    const int warp = tid >> 5;
    const int lane = tid & 31;
    const int g    = lane >> 2;
    const int t    = lane & 3;
    const int m0   = warp * 16;
    const int bh   = blockIdx.y;
    const int qt   = blockIdx.x;

    // ---- load Q (scaled by 1/sqrt(64), folded in pre-round) ----
    {
        const float* qp = q + ((size_t)bh * SEQ + qt * 64) * DEP;
#pragma unroll
        for (int p = 0; p < 8; p++) {
            int f4  = p * 128 + tid;
            int row = f4 >> 4;
            int c4  = (f4 & 15) << 2;
            float4 vv = *(const float4*)(qp + (size_t)row * DEP + c4);
            uint32_t* dst = &Qs[row * Q_ST + c4];
            dst[0] = f2tf(vv.x * 0.125f); dst[1] = f2tf(vv.y * 0.125f);
            dst[2] = f2tf(vv.z * 0.125f); dst[3] = f2tf(vv.w * 0.125f);
        }
    }

    float mrow0 = -1e30f, mrow1 = -1e30f, l0 = 0.f, l1 = 0.f;
    float O[8][4];
#pragma unroll
    for (int dt = 0; dt < 8; dt++)
#pragma unroll
        for (int r = 0; r < 4; r++) O[dt][r] = 0.f;

    const float* kbase = k + (size_t)bh * SEQ * DEP;
    const float* vbase = v + (size_t)bh * SEQ * DEP;

    for (int t0 = 0; t0 < SEQ; t0 += 64) {
        __syncthreads();   // previous-tile reads done before overwrite (also fences Qs fill)
        // ---- load K and V tiles (64x64 each) ----
#pragma unroll
        for (int p = 0; p < 8; p++) {
            int f4  = p * 128 + tid;
            int row = f4 >> 4;
            int c4  = (f4 & 15) << 2;
            float4 kv = *(const float4*)(kbase + (size_t)(t0 + row) * DEP + c4);
            float4 vv = *(const float4*)(vbase + (size_t)(t0 + row) * DEP + c4);
            uint32_t* kd = &Ks[row * Q_ST + c4];
            kd[0] = f2tf(kv.x); kd[1] = f2tf(kv.y); kd[2] = f2tf(kv.z); kd[3] = f2tf(kv.w);
            uint32_t* vd = &Vs[row * V_ST + c4];
            vd[0] = f2tf(vv.x); vd[1] = f2tf(vv.y); vd[2] = f2tf(vv.z); vd[3] = f2tf(vv.w);
        }
        __syncthreads();

        // ---- S = Q K^T : warp computes rows [m0, m0+16) x 64 keys ----
        float s[8][4];
#pragma unroll
        for (int nt = 0; nt < 8; nt++)
#pragma unroll
            for (int r = 0; r < 4; r++) s[nt][r] = 0.f;

#pragma unroll
        for (int kk = 0; kk < 8; kk++) {
            const int kb = kk * 8;
            uint32_t a0 = Qs[(m0 + g)     * Q_ST + kb + t];
            uint32_t a1 = Qs[(m0 + g + 8) * Q_ST + kb + t];
            uint32_t a2 = Qs[(m0 + g)     * Q_ST + kb + t + 4];
            uint32_t a3 = Qs[(m0 + g + 8) * Q_ST + kb + t + 4];
#pragma unroll
            for (int nt = 0; nt < 8; nt++) {
                uint32_t b0 = Ks[(nt * 8 + g) * Q_ST + kb + t];
                uint32_t b1 = Ks[(nt * 8 + g) * Q_ST + kb + t + 4];
                mma8(s[nt], a0, a1, a2, a3, b0, b1);
            }
        }

        // ---- online softmax (rows g and g+8) ----
        float mx0 = -1e30f, mx1 = -1e30f;
#pragma unroll
        for (int nt = 0; nt < 8; nt++) {
            mx0 = fmaxf(mx0, fmaxf(s[nt][0], s[nt][1]));
            mx1 = fmaxf(mx1, fmaxf(s[nt][2], s[nt][3]));
        }
        mx0 = fmaxf(mx0, __shfl_xor_sync(0xffffffffu, mx0, 1));
        mx0 = fmaxf(mx0, __shfl_xor_sync(0xffffffffu, mx0, 2));
        mx1 = fmaxf(mx1, __shfl_xor_sync(0xffffffffu, mx1, 1));
        mx1 = fmaxf(mx1, __shfl_xor_sync(0xffffffffu, mx1, 2));

        float mn0 = fmaxf(mrow0, mx0);
        float mn1 = fmaxf(mrow1, mx1);
        float corr0 = __expf(mrow0 - mn0);
        float corr1 = __expf(mrow1 - mn1);

        float sum0 = 0.f, sum1 = 0.f;
#pragma unroll
        for (int nt = 0; nt < 8; nt++) {
            s[nt][0] = __expf(s[nt][0] - mn0);
            s[nt][1] = __expf(s[nt][1] - mn0);
            s[nt][2] = __expf(s[nt][2] - mn1);
            s[nt][3] = __expf(s[nt][3] - mn1);
            sum0 += s[nt][0] + s[nt][1];
            sum1 += s[nt][2] + s[nt][3];
        }
        sum0 += __shfl_xor_sync(0xffffffffu, sum0, 1);
        sum0 += __shfl_xor_sync(0xffffffffu, sum0, 2);
        sum1 += __shfl_xor_sync(0xffffffffu, sum1, 1);
        sum1 += __shfl_xor_sync(0xffffffffu, sum1, 2);
        l0 = l0 * corr0 + sum0;
        l1 = l1 * corr1 + sum1;

#pragma unroll
        for (int dt = 0; dt < 8; dt++) {
            O[dt][0] *= corr0; O[dt][1] *= corr0;
            O[dt][2] *= corr1; O[dt][3] *= corr1;
        }

        // ---- write P (tf32) to warp-private Ps rows ----
#pragma unroll
        for (int nt = 0; nt < 8; nt++) {
            uint2 p01 = make_uint2(f2tf(s[nt][0]), f2tf(s[nt][1]));
            uint2 p23 = make_uint2(f2tf(s[nt][2]), f2tf(s[nt][3]));
            *(uint2*)&Ps[(m0 + g)     * Q_ST + nt * 8 + 2 * t] = p01;
            *(uint2*)&Ps[(m0 + g + 8) * Q_ST + nt * 8 + 2 * t] = p23;
        }
        __syncwarp();

        // ---- O += P V ----
#pragma unroll
        for (int kk = 0; kk < 8; kk++) {
            const int kb = kk * 8;
            uint32_t a0 = Ps[(m0 + g)     * Q_ST + kb + t];
            uint32_t a1 = Ps[(m0 + g + 8) * Q_ST + kb + t];
            uint32_t a2 = Ps[(m0 + g)     * Q_ST + kb + t + 4];
            uint32_t a3 = Ps[(m0 + g + 8) * Q_ST + kb + t + 4];
#pragma unroll
            for (int dt = 0; dt < 8; dt++) {
                uint32_t b0 = Vs[(kb + t)     * V_ST + dt * 8 + g];
                uint32_t b1 = Vs[(kb + t + 4) * V_ST + dt * 8 + g];
                mma8(O[dt], a0, a1, a2, a3, b0, b1);
            }
        }

        mrow0 = mn0;
        mrow1 = mn1;
    }

    // ---- normalize + store to multi [B][S][H*64] ----
    float inv0 = 1.f / l0, inv1 = 1.f / l1;
    int b = bh >> 4, h = bh & 15;
    int srow = qt * 64 + m0 + g;
    float* op = multi + ((size_t)(b * SEQ) + srow) * DM + h * DEP;
#pragma unroll
    for (int dt = 0; dt < 8; dt++) {
        int col = dt * 8 + 2 * t;
        *(float2*)(op + col)             = make_float2(O[dt][0] * inv0, O[dt][1] * inv0);
        *(float2*)(op + 8 * (size_t)DM + col) = make_float2(O[dt][2] * inv1, O[dt][3] * inv1);
    }
}

// ---------------------------------------------------------------------------
// Launch: 3 QKV GEMMs -> attention -> output GEMM. All graph-capturable.
// ---------------------------------------------------------------------------
extern "C" void kernel_launch(void* const* d_in, const int* in_sizes, int n_in,
                              void* d_out, int out_size)
{
    const float* x  = (const float*)d_in[0];
    const float* Wq = (const float*)d_in[1];
    const float* bq = (const float*)d_in[2];
    const float* Wk = (const float*)d_in[3];
    const float* bk = (const float*)d_in[4];
    const float* Wv = (const float*)d_in[5];
    const float* bv = (const float*)d_in[6];
    const float* Wo = (const float*)d_in[7];
    const float* bo = (const float*)d_in[8];
    float* out = (float*)d_out;

    float *qb, *kb, *vb, *mb;
    cudaGetSymbolAddress((void**)&qb, g_q);
    cudaGetSymbolAddress((void**)&kb, g_k);
    cudaGetSymbolAddress((void**)&vb, g_v);
    cudaGetSymbolAddress((void**)&mb, g_multi);

    const int att_smem = ATT_SMEM_WORDS * 4;   // 70656 bytes
    cudaFuncSetAttribute(attn_tc, cudaFuncAttributeMaxDynamicSharedMemorySize, att_smem);

    dim3 gg(DM / 128, MROWS / 128);   // (8, 64)
    gemm_tf32<<<gg, 256>>>(x, Wq, bq, qb, 1);
    gemm_tf32<<<gg, 256>>>(x, Wk, bk, kb, 1);
    gemm_tf32<<<gg, 256>>>(x, Wv, bv, vb, 1);

    dim3 ga(SEQ / 64, BHN);           // (32, 64)
    attn_tc<<<ga, 128, att_smem>>>(qb, kb, vb, mb);

    gemm_tf32<<<gg, 256>>>(mb, Wo, bo, out, 0);
}

// round 8
// speedup vs baseline: 4.3405x; 1.1197x over previous
#include <cuda_runtime.h>
#include <math.h>
#include <stdint.h>

#define SEQ    2048
#define DM     1024
#define NH     16
#define DEP    64
#define BATCHN 4
#define MROWS  (BATCHN*SEQ)   /* 8192 */
#define BHN    (BATCHN*NH)    /* 64   */

// Scratch (allocation-free rule: __device__ globals)
__device__ float g_q[(size_t)BHN*SEQ*DEP];
__device__ float g_k[(size_t)BHN*SEQ*DEP];
__device__ float g_v[(size_t)BHN*SEQ*DEP];
__device__ float g_multi[(size_t)MROWS*DM];

// ---------------------------------------------------------------------------
// tf32 helpers
// ---------------------------------------------------------------------------
__device__ __forceinline__ uint32_t f2tf(float x) {
    uint32_t u;
    asm("cvt.rna.tf32.f32 %0, %1;" : "=r"(u) : "f"(x));
    return u;
}

// D += A(16x8, row) * B(8x8, col)  tf32 -> f32
__device__ __forceinline__ void mma8(float* c,
    uint32_t a0, uint32_t a1, uint32_t a2, uint32_t a3,
    uint32_t b0, uint32_t b1)
{
    asm volatile(
        "mma.sync.aligned.m16n8k8.row.col.f32.tf32.tf32.f32 "
        "{%0,%1,%2,%3}, {%4,%5,%6,%7}, {%8,%9}, {%0,%1,%2,%3};"
        : "+f"(c[0]), "+f"(c[1]), "+f"(c[2]), "+f"(c[3])
        : "r"(a0), "r"(a1), "r"(a2), "r"(a3), "r"(b0), "r"(b1));
}

// ---------------------------------------------------------------------------
// tf32 GEMM body, double-buffered smem + register-staged prefetch.
// C[8192,1024] = A[8192,1024] * W + bias
// MODE 0: W row-major [K,N] (Wo), C row-major [M,N]
// MODE 1: W = [H][K][64] stacked, C stored as [BH][S][64]
// 128x128 block, BK=32, 256 threads (8 warps of 64x32), m16n8k8.
// ---------------------------------------------------------------------------
#define AS_ST 36
#define BS_ST 136
#define ABUF  (128 * AS_ST)                 /* 4608 words */
#define BBUF  (32  * BS_ST)                 /* 4352 words */
#define GEMM_SMEM_BYTES (2 * (ABUF + BBUF) * 4)   /* 71680 */

template<int MODE>
__device__ __forceinline__ void gemm_body(
    const float* __restrict__ A, const float* __restrict__ W,
    const float* __restrict__ bias, float* __restrict__ C)
{
    extern __shared__ uint32_t gsm[];
    uint32_t* As = gsm;                // [2][ABUF]
    uint32_t* Bs = gsm + 2 * ABUF;     // [2][BBUF]

    const int tid  = threadIdx.x;
    const int m0   = blockIdx.y * 128;
    const int n0   = blockIdx.x * 128;
    const int warp = tid >> 5;
    const int lane = tid & 31;
    const int g    = lane >> 2;
    const int t    = lane & 3;
    const int wm   = (warp >> 2) * 64;   // 0 or 64
    const int wn   = (warp & 3) * 32;    // 0,32,64,96

    // load/store addressing (p-invariant parts)
    const int arow = tid >> 3;            // + p*32
    const int ac4  = (tid & 7) << 2;
    const int brow = tid >> 5;            // + p*8
    const int bc4  = (tid & 31) << 2;

    float acc[4][4][4];
#pragma unroll
    for (int mi = 0; mi < 4; mi++)
#pragma unroll
        for (int ni = 0; ni < 4; ni++)
#pragma unroll
            for (int r = 0; r < 4; r++) acc[mi][ni][r] = 0.f;

    float4 ar[4], br[4];

    auto load_tiles = [&](int kt) {
#pragma unroll
        for (int p = 0; p < 4; p++)
            ar[p] = *(const float4*)(A + (size_t)(m0 + p * 32 + arow) * DM + kt + ac4);
#pragma unroll
        for (int p = 0; p < 4; p++) {
            const float* src;
            int row = p * 8 + brow;
            if (MODE == 0) {
                src = W + (size_t)(kt + row) * DM + n0 + bc4;
            } else {
                int n = n0 + bc4;
                src = W + (size_t)(n >> 6) * (DM * DEP) + (size_t)(kt + row) * DEP + (n & 63);
            }
            br[p] = *(const float4*)src;
        }
    };

    auto store_tiles = [&](int buf) {
        uint32_t* Ab = As + buf * ABUF;
        uint32_t* Bb = Bs + buf * BBUF;
#pragma unroll
        for (int p = 0; p < 4; p++) {
            uint32_t* d = &Ab[(p * 32 + arow) * AS_ST + ac4];
            d[0] = f2tf(ar[p].x); d[1] = f2tf(ar[p].y);
            d[2] = f2tf(ar[p].z); d[3] = f2tf(ar[p].w);
        }
#pragma unroll
        for (int p = 0; p < 4; p++) {
            uint32_t* d = &Bb[(p * 8 + brow) * BS_ST + bc4];
            d[0] = f2tf(br[p].x); d[1] = f2tf(br[p].y);
            d[2] = f2tf(br[p].z); d[3] = f2tf(br[p].w);
        }
    };

    auto compute = [&](int buf) {
        const uint32_t* Ab = As + buf * ABUF;
        const uint32_t* Bb = Bs + buf * BBUF;
#pragma unroll
        for (int kk = 0; kk < 4; kk++) {
            const int k = kk * 8;
            uint32_t a[4][4];
#pragma unroll
            for (int mi = 0; mi < 4; mi++) {
                int r0 = wm + mi * 16 + g;
                a[mi][0] = Ab[(r0)     * AS_ST + k + t];
                a[mi][1] = Ab[(r0 + 8) * AS_ST + k + t];
                a[mi][2] = Ab[(r0)     * AS_ST + k + t + 4];
                a[mi][3] = Ab[(r0 + 8) * AS_ST + k + t + 4];
            }
#pragma unroll
            for (int ni = 0; ni < 4; ni++) {
                uint32_t b0 = Bb[(k + t)     * BS_ST + wn + ni * 8 + g];
                uint32_t b1 = Bb[(k + t + 4) * BS_ST + wn + ni * 8 + g];
#pragma unroll
                for (int mi = 0; mi < 4; mi++)
                    mma8(acc[mi][ni], a[mi][0], a[mi][1], a[mi][2], a[mi][3], b0, b1);
            }
        }
    };

    // pipeline: prefetch(kt) overlaps compute(kt-32)
    load_tiles(0);
    store_tiles(0);
    __syncthreads();
    int p = 0;
#pragma unroll 1
    for (int kt = 32; kt < DM; kt += 32) {
        load_tiles(kt);        // gmem -> regs (latency hidden under compute)
        compute(p);
        store_tiles(p ^ 1);    // safe: buf p^1 last read before previous sync
        __syncthreads();
        p ^= 1;
    }
    compute(p);

    // ---- epilogue: bias + store ----
#pragma unroll
    for (int mi = 0; mi < 4; mi++) {
        int row0 = m0 + wm + mi * 16 + g;
#pragma unroll
        for (int ni = 0; ni < 4; ni++) {
            int col = n0 + wn + ni * 8 + 2 * t;
            float bx = bias[col], by = bias[col + 1];
#pragma unroll
            for (int h = 0; h < 2; h++) {
                int row = row0 + h * 8;
                float2 val;
                val.x = acc[mi][ni][h * 2 + 0] + bx;
                val.y = acc[mi][ni][h * 2 + 1] + by;
                if (MODE == 0) {
                    *(float2*)&C[(size_t)row * DM + col] = val;
                } else {
                    int b = row >> 11, s = row & 2047;
                    int hh = col >> 6, e = col & 63;
                    *(float2*)&C[(((size_t)(b * NH + hh)) * SEQ + s) * DEP + e] = val;
                }
            }
        }
    }
}

// Fused QKV: blockIdx.z selects projection (kills wave-quantization tail)
__global__ __launch_bounds__(256) void gemm_qkv(
    const float* __restrict__ x,
    const float* __restrict__ Wq, const float* __restrict__ Wk, const float* __restrict__ Wv,
    const float* __restrict__ bq, const float* __restrict__ bk, const float* __restrict__ bv,
    float* __restrict__ qo, float* __restrict__ ko, float* __restrict__ vo)
{
    int z = blockIdx.z;
    const float* W = (z == 0) ? Wq : (z == 1) ? Wk : Wv;
    const float* b = (z == 0) ? bq : (z == 1) ? bk : bv;
    float*       C = (z == 0) ? qo : (z == 1) ? ko : vo;
    gemm_body<1>(x, W, b, C);
}

__global__ __launch_bounds__(256) void gemm_out(
    const float* __restrict__ A, const float* __restrict__ W,
    const float* __restrict__ bias, float* __restrict__ C)
{
    gemm_body<0>(A, W, bias, C);
}

// ---------------------------------------------------------------------------
// Tensor-core flash attention (tf32 MMA, fp32 online softmax).
// Block = 128 threads (4 warps), each warp owns 32 query rows (2 m-tiles):
// B-fragments (K,V) reused 2x, softmax/index ALU amortized 2x.
// Q tile 128x64 per block, key tiles of 64. grid = (SEQ/128, BH).
// Smem: Qs/Ks/Ps stride 68 (4g+t conflict-free), Vs stride 72 (8t+g c.f.)
// ---------------------------------------------------------------------------
#define Q_ST 68
#define V_ST 72
#define QROWS 128
#define OFF_Q 0
#define OFF_K (QROWS * Q_ST)             /* 8704  */
#define OFF_P (OFF_K + 64 * Q_ST)        /* 13056 */
#define OFF_V (OFF_P + QROWS * Q_ST)     /* 21760 */
#define ATT_SMEM_WORDS (OFF_V + 64 * V_ST)  /* 26368 -> 105472 B */

__global__ __launch_bounds__(128) void attn_tc(
    const float* __restrict__ q, const float* __restrict__ k,
    const float* __restrict__ v, float* __restrict__ multi)
{
    extern __shared__ uint32_t sm[];
    uint32_t* Qs = sm + OFF_Q;
    uint32_t* Ks = sm + OFF_K;
    uint32_t* Ps = sm + OFF_P;
    uint32_t* Vs = sm + OFF_V;

    const int tid  = threadIdx.x;
    const int warp = tid >> 5;
    const int lane = tid & 31;
    const int g    = lane >> 2;
    const int t    = lane & 3;
    const int bh   = blockIdx.y;
    const int qt   = blockIdx.x;
    const int mb[2] = { warp * 32, warp * 32 + 16 };

    // ---- load Q 128x64 (scale 1/sqrt(64) folded pre-round) ----
    {
        const float* qp = q + ((size_t)bh * SEQ + qt * QROWS) * DEP;
#pragma unroll
        for (int p = 0; p < 16; p++) {
            int f4  = p * 128 + tid;
            int row = f4 >> 4;
            int c4  = (f4 & 15) << 2;
            float4 vv = *(const float4*)(qp + (size_t)row * DEP + c4);
            uint32_t* dst = &Qs[row * Q_ST + c4];
            dst[0] = f2tf(vv.x * 0.125f); dst[1] = f2tf(vv.y * 0.125f);
            dst[2] = f2tf(vv.z * 0.125f); dst[3] = f2tf(vv.w * 0.125f);
        }
    }

    float mr[2][2], l[2][2];
    float O[2][8][4];
#pragma unroll
    for (int mi = 0; mi < 2; mi++) {
        mr[mi][0] = mr[mi][1] = -1e30f;
        l[mi][0] = l[mi][1] = 0.f;
#pragma unroll
        for (int dt = 0; dt < 8; dt++)
#pragma unroll
            for (int r = 0; r < 4; r++) O[mi][dt][r] = 0.f;
    }

    const float* kbase = k + (size_t)bh * SEQ * DEP;
    const float* vbase = v + (size_t)bh * SEQ * DEP;

#pragma unroll 1
    for (int t0 = 0; t0 < SEQ; t0 += 64) {
        __syncthreads();   // prev-tile reads done before overwrite (also fences Qs fill)
#pragma unroll
        for (int p = 0; p < 8; p++) {
            int f4  = p * 128 + tid;
            int row = f4 >> 4;
            int c4  = (f4 & 15) << 2;
            float4 kv = *(const float4*)(kbase + (size_t)(t0 + row) * DEP + c4);
            float4 vv = *(const float4*)(vbase + (size_t)(t0 + row) * DEP + c4);
            uint32_t* kd = &Ks[row * Q_ST + c4];
            kd[0] = f2tf(kv.x); kd[1] = f2tf(kv.y); kd[2] = f2tf(kv.z); kd[3] = f2tf(kv.w);
            uint32_t* vd = &Vs[row * V_ST + c4];
            vd[0] = f2tf(vv.x); vd[1] = f2tf(vv.y); vd[2] = f2tf(vv.z); vd[3] = f2tf(vv.w);
        }
        __syncthreads();

        // ---- S = Q K^T : 2 m-tiles share every K fragment ----
        float s[2][8][4];
#pragma unroll
        for (int mi = 0; mi < 2; mi++)
#pragma unroll
            for (int nt = 0; nt < 8; nt++)
#pragma unroll
                for (int r = 0; r < 4; r++) s[mi][nt][r] = 0.f;

#pragma unroll
        for (int kk = 0; kk < 8; kk++) {
            const int kb = kk * 8;
            uint32_t a[2][4];
#pragma unroll
            for (int mi = 0; mi < 2; mi++) {
                a[mi][0] = Qs[(mb[mi] + g)     * Q_ST + kb + t];
                a[mi][1] = Qs[(mb[mi] + g + 8) * Q_ST + kb + t];
                a[mi][2] = Qs[(mb[mi] + g)     * Q_ST + kb + t + 4];
                a[mi][3] = Qs[(mb[mi] + g + 8) * Q_ST + kb + t + 4];
            }
#pragma unroll
            for (int nt = 0; nt < 8; nt++) {
                uint32_t b0 = Ks[(nt * 8 + g) * Q_ST + kb + t];
                uint32_t b1 = Ks[(nt * 8 + g) * Q_ST + kb + t + 4];
                mma8(s[0][nt], a[0][0], a[0][1], a[0][2], a[0][3], b0, b1);
                mma8(s[1][nt], a[1][0], a[1][1], a[1][2], a[1][3], b0, b1);
            }
        }

        // ---- online softmax + P write, per m-tile ----
#pragma unroll
        for (int mi = 0; mi < 2; mi++) {
            float mx0 = -1e30f, mx1 = -1e30f;
#pragma unroll
            for (int nt = 0; nt < 8; nt++) {
                mx0 = fmaxf(mx0, fmaxf(s[mi][nt][0], s[mi][nt][1]));
                mx1 = fmaxf(mx1, fmaxf(s[mi][nt][2], s[mi][nt][3]));
            }
            mx0 = fmaxf(mx0, __shfl_xor_sync(0xffffffffu, mx0, 1));
            mx0 = fmaxf(mx0, __shfl_xor_sync(0xffffffffu, mx0, 2));
            mx1 = fmaxf(mx1, __shfl_xor_sync(0xffffffffu, mx1, 1));
            mx1 = fmaxf(mx1, __shfl_xor_sync(0xffffffffu, mx1, 2));

            float mn0 = fmaxf(mr[mi][0], mx0);
            float mn1 = fmaxf(mr[mi][1], mx1);
            float corr0 = __expf(mr[mi][0] - mn0);
            float corr1 = __expf(mr[mi][1] - mn1);

            float sum0 = 0.f, sum1 = 0.f;
#pragma unroll
            for (int nt = 0; nt < 8; nt++) {
                s[mi][nt][0] = __expf(s[mi][nt][0] - mn0);
                s[mi][nt][1] = __expf(s[mi][nt][1] - mn0);
                s[mi][nt][2] = __expf(s[mi][nt][2] - mn1);
                s[mi][nt][3] = __expf(s[mi][nt][3] - mn1);
                sum0 += s[mi][nt][0] + s[mi][nt][1];
                sum1 += s[mi][nt][2] + s[mi][nt][3];
            }
            sum0 += __shfl_xor_sync(0xffffffffu, sum0, 1);
            sum0 += __shfl_xor_sync(0xffffffffu, sum0, 2);
            sum1 += __shfl_xor_sync(0xffffffffu, sum1, 1);
            sum1 += __shfl_xor_sync(0xffffffffu, sum1, 2);
            l[mi][0] = l[mi][0] * corr0 + sum0;
            l[mi][1] = l[mi][1] * corr1 + sum1;

#pragma unroll
            for (int dt = 0; dt < 8; dt++) {
                O[mi][dt][0] *= corr0; O[mi][dt][1] *= corr0;
                O[mi][dt][2] *= corr1; O[mi][dt][3] *= corr1;
            }

#pragma unroll
            for (int nt = 0; nt < 8; nt++) {
                uint2 p01 = make_uint2(f2tf(s[mi][nt][0]), f2tf(s[mi][nt][1]));
                uint2 p23 = make_uint2(f2tf(s[mi][nt][2]), f2tf(s[mi][nt][3]));
                *(uint2*)&Ps[(mb[mi] + g)     * Q_ST + nt * 8 + 2 * t] = p01;
                *(uint2*)&Ps[(mb[mi] + g + 8) * Q_ST + nt * 8 + 2 * t] = p23;
            }
            mr[mi][0] = mn0;
            mr[mi][1] = mn1;
        }
        __syncwarp();   // Ps rows are warp-private

        // ---- O += P V : 2 m-tiles share every V fragment ----
#pragma unroll
        for (int kk = 0; kk < 8; kk++) {
            const int kb = kk * 8;
            uint32_t a[2][4];
#pragma unroll
            for (int mi = 0; mi < 2; mi++) {
                a[mi][0] = Ps[(mb[mi] + g)     * Q_ST + kb + t];
                a[mi][1] = Ps[(mb[mi] + g + 8) * Q_ST + kb + t];
                a[mi][2] = Ps[(mb[mi] + g)     * Q_ST + kb + t + 4];
                a[mi][3] = Ps[(mb[mi] + g + 8) * Q_ST + kb + t + 4];
            }
#pragma unroll
            for (int dt = 0; dt < 8; dt++) {
                uint32_t b0 = Vs[(kb + t)     * V_ST + dt * 8 + g];
                uint32_t b1 = Vs[(kb + t + 4) * V_ST + dt * 8 + g];
                mma8(O[0][dt], a[0][0], a[0][1], a[0][2], a[0][3], b0, b1);
                mma8(O[1][dt], a[1][0], a[1][1], a[1][2], a[1][3], b0, b1);
            }
        }
    }

    // ---- normalize + store to multi [B][S][H*64] ----
    int b = bh >> 4, h = bh & 15;
#pragma unroll
    for (int mi = 0; mi < 2; mi++) {
        float inv0 = 1.f / l[mi][0], inv1 = 1.f / l[mi][1];
        int srow = qt * QROWS + mb[mi] + g;
        float* op = multi + ((size_t)(b * SEQ) + srow) * DM + h * DEP;
#pragma unroll
        for (int dt = 0; dt < 8; dt++) {
            int col = dt * 8 + 2 * t;
            *(float2*)(op + col) =
                make_float2(O[mi][dt][0] * inv0, O[mi][dt][1] * inv0);
            *(float2*)(op + 8 * (size_t)DM + col) =
                make_float2(O[mi][dt][2] * inv1, O[mi][dt][3] * inv1);
        }
    }
}

// ---------------------------------------------------------------------------
// Launch: fused QKV GEMM -> attention -> output GEMM. Graph-capturable.
// ---------------------------------------------------------------------------
extern "C" void kernel_launch(void* const* d_in, const int* in_sizes, int n_in,
                              void* d_out, int out_size)
{
    const float* x  = (const float*)d_in[0];
    const float* Wq = (const float*)d_in[1];
    const float* bq = (const float*)d_in[2];
    const float* Wk = (const float*)d_in[3];
    const float* bk = (const float*)d_in[4];
    const float* Wv = (const float*)d_in[5];
    const float* bv = (const float*)d_in[6];
    const float* Wo = (const float*)d_in[7];
    const float* bo = (const float*)d_in[8];
    float* out = (float*)d_out;

    float *qb, *kb, *vb, *mb;
    cudaGetSymbolAddress((void**)&qb, g_q);
    cudaGetSymbolAddress((void**)&kb, g_k);
    cudaGetSymbolAddress((void**)&vb, g_v);
    cudaGetSymbolAddress((void**)&mb, g_multi);

    const int att_smem = ATT_SMEM_WORDS * 4;   // 105472 bytes
    cudaFuncSetAttribute(attn_tc, cudaFuncAttributeMaxDynamicSharedMemorySize, att_smem);
    cudaFuncSetAttribute(gemm_qkv, cudaFuncAttributeMaxDynamicSharedMemorySize, GEMM_SMEM_BYTES);
    cudaFuncSetAttribute(gemm_out, cudaFuncAttributeMaxDynamicSharedMemorySize, GEMM_SMEM_BYTES);

    dim3 gq(DM / 128, MROWS / 128, 3);   // (8, 64, 3) fused QKV
    gemm_qkv<<<gq, 256, GEMM_SMEM_BYTES>>>(x, Wq, Wk, Wv, bq, bk, bv, qb, kb, vb);

    dim3 ga(SEQ / QROWS, BHN);           // (16, 64)
    attn_tc<<<ga, 128, att_smem>>>(qb, kb, vb, mb);

    dim3 gg(DM / 128, MROWS / 128);      // (8, 64)
    gemm_out<<<gg, 256, GEMM_SMEM_BYTES>>>(mb, Wo, bo, out);
}

// round 10
// speedup vs baseline: 7.5265x; 1.7340x over previous
#include <cuda_runtime.h>
#include <math.h>
#include <stdint.h>

#define SEQ    2048
#define DM     1024
#define NH     16
#define DEP    64
#define BATCHN 4
#define MROWS  (BATCHN*SEQ)   /* 8192 */
#define BHN    (BATCHN*NH)    /* 64   */

// Scratch (allocation-free rule: __device__ globals). q/k/v/multi hold tf32
// bit-patterns (valid fp32 values with low mantissa bits zero).
__device__ uint32_t g_q[(size_t)BHN*SEQ*DEP];
__device__ uint32_t g_k[(size_t)BHN*SEQ*DEP];
__device__ uint32_t g_v[(size_t)BHN*SEQ*DEP];
__device__ uint32_t g_multi[(size_t)MROWS*DM];
// Pre-converted tf32 operands
__device__ uint32_t g_xt [(size_t)MROWS*DM];
__device__ uint32_t g_wqt[(size_t)DM*DM];
__device__ uint32_t g_wkt[(size_t)DM*DM];
__device__ uint32_t g_wvt[(size_t)DM*DM];
__device__ uint32_t g_wot[(size_t)DM*DM];

// ---------------------------------------------------------------------------
// helpers
// ---------------------------------------------------------------------------
__device__ __forceinline__ uint32_t f2tf(float x) {
    uint32_t u;
    asm("cvt.rna.tf32.f32 %0, %1;" : "=r"(u) : "f"(x));
    return u;
}
__device__ __forceinline__ uint32_t smem_u32(const void* p) {
    return (uint32_t)__cvta_generic_to_shared(p);
}
#define CP16(dst_u32, src_ptr) \
    asm volatile("cp.async.cg.shared.global [%0], [%1], 16;" :: "r"(dst_u32), "l"(src_ptr))
#define CP_COMMIT() asm volatile("cp.async.commit_group;")
#define CP_WAIT0()  asm volatile("cp.async.wait_group 0;")
#define CP_WAIT1()  asm volatile("cp.async.wait_group 1;")

// D += A(16x8, row) * B(8x8, col)  tf32 -> f32
__device__ __forceinline__ void mma8(float* c,
    uint32_t a0, uint32_t a1, uint32_t a2, uint32_t a3,
    uint32_t b0, uint32_t b1)
{
    asm volatile(
        "mma.sync.aligned.m16n8k8.row.col.f32.tf32.tf32.f32 "
        "{%0,%1,%2,%3}, {%4,%5,%6,%7}, {%8,%9}, {%0,%1,%2,%3};"
        : "+f"(c[0]), "+f"(c[1]), "+f"(c[2]), "+f"(c[3])
        : "r"(a0), "r"(a1), "r"(a2), "r"(a3), "r"(b0), "r"(b1));
}

// ---------------------------------------------------------------------------
// Elementwise fp32 -> tf32-bits conversion (pre-pass)
// ---------------------------------------------------------------------------
__global__ __launch_bounds__(256) void conv_tf32(
    const float4* __restrict__ src, uint4* __restrict__ dst, int n4)
{
    int i = blockIdx.x * blockDim.x + threadIdx.x;
    if (i < n4) {
        float4 v = src[i];
        dst[i] = make_uint4(f2tf(v.x), f2tf(v.y), f2tf(v.z), f2tf(v.w));
    }
}

// ---------------------------------------------------------------------------
// tf32 GEMM, cp.async 2-stage double buffer, 2 CTAs/SM.
// C[8192,1024] = A[8192,1024] * W + bias.  A/W already tf32 bits.
// MODE 0: W row-major [K,N], C = final fp32 output
// MODE 1: W = [H][K][64] stacked, C = tf32 bits stored as [BH][S][64]
// 128x128 block, BK=32, 256 threads (8 warps of 64x32), m16n8k8.
// ---------------------------------------------------------------------------
#define AS_ST 36
#define BS_ST 136
#define ABUF  (128 * AS_ST)                 /* 4608 words */
#define BBUF  (32  * BS_ST)                 /* 4352 words */
#define GEMM_SMEM_BYTES (2 * (ABUF + BBUF) * 4)   /* 71680 */
#define NCHUNK (DM / 32)                    /* 32 */

template<int MODE>
__device__ __forceinline__ void gemm_body(
    const uint32_t* __restrict__ A, const uint32_t* __restrict__ W,
    const float* __restrict__ bias, void* __restrict__ Cv)
{
    extern __shared__ uint32_t gsm[];
    uint32_t* As = gsm;                // [2][ABUF]
    uint32_t* Bs = gsm + 2 * ABUF;     // [2][BBUF]

    const int tid  = threadIdx.x;
    const int m0   = blockIdx.y * 128;
    const int n0   = blockIdx.x * 128;
    const int warp = tid >> 5;
    const int lane = tid & 31;
    const int g    = lane >> 2;
    const int t    = lane & 3;
    const int wm   = (warp >> 2) * 64;   // 0 or 64
    const int wn   = (warp & 3) * 32;    // 0,32,64,96

    const int arow = tid >> 3;            // + p*32
    const int ac4  = (tid & 7) << 2;
    const int brow = tid >> 5;            // + p*8
    const int bc4  = (tid & 31) << 2;

    float acc[4][4][4];
#pragma unroll
    for (int mi = 0; mi < 4; mi++)
#pragma unroll
        for (int ni = 0; ni < 4; ni++)
#pragma unroll
            for (int r = 0; r < 4; r++) acc[mi][ni][r] = 0.f;

    auto issue = [&](int kt, int buf) {
        uint32_t* Ab = As + buf * ABUF;
        uint32_t* Bb = Bs + buf * BBUF;
#pragma unroll
        for (int p = 0; p < 4; p++) {
            int row = p * 32 + arow;
            CP16(smem_u32(&Ab[row * AS_ST + ac4]),
                 A + (size_t)(m0 + row) * DM + kt + ac4);
        }
#pragma unroll
        for (int p = 0; p < 4; p++) {
            int row = p * 8 + brow;
            const uint32_t* src;
            if (MODE == 0) {
                src = W + (size_t)(kt + row) * DM + n0 + bc4;
            } else {
                int n = n0 + bc4;
                src = W + (size_t)(n >> 6) * (DM * DEP) + (size_t)(kt + row) * DEP + (n & 63);
            }
            CP16(smem_u32(&Bb[row * BS_ST + bc4]), src);
        }
        CP_COMMIT();
    };

    auto compute = [&](int buf) {
        const uint32_t* Ab = As + buf * ABUF;
        const uint32_t* Bb = Bs + buf * BBUF;
#pragma unroll
        for (int kk = 0; kk < 4; kk++) {
            const int k = kk * 8;
            uint32_t a[4][4];
#pragma unroll
            for (int mi = 0; mi < 4; mi++) {
                int r0 = wm + mi * 16 + g;
                a[mi][0] = Ab[(r0)     * AS_ST + k + t];
                a[mi][1] = Ab[(r0 + 8) * AS_ST + k + t];
                a[mi][2] = Ab[(r0)     * AS_ST + k + t + 4];
                a[mi][3] = Ab[(r0 + 8) * AS_ST + k + t + 4];
            }
#pragma unroll
            for (int ni = 0; ni < 4; ni++) {
                uint32_t b0 = Bb[(k + t)     * BS_ST + wn + ni * 8 + g];
                uint32_t b1 = Bb[(k + t + 4) * BS_ST + wn + ni * 8 + g];
#pragma unroll
                for (int mi = 0; mi < 4; mi++)
                    mma8(acc[mi][ni], a[mi][0], a[mi][1], a[mi][2], a[mi][3], b0, b1);
            }
        }
    };

    // 2-stage cp.async pipeline: issue c+1 before waiting on c.
    issue(0, 0);
#pragma unroll 1
    for (int c = 0; c < NCHUNK; c++) {
        if (c + 1 < NCHUNK) {
            issue((c + 1) * 32, (c + 1) & 1);
            CP_WAIT1();              // chunk c landed
        } else {
            CP_WAIT0();
        }
        __syncthreads();             // all warps see buf c
        compute(c & 1);
        __syncthreads();             // done reading before overwrite at c+2
    }

    // ---- epilogue: bias + store ----
#pragma unroll
    for (int mi = 0; mi < 4; mi++) {
        int row0 = m0 + wm + mi * 16 + g;
#pragma unroll
        for (int ni = 0; ni < 4; ni++) {
            int col = n0 + wn + ni * 8 + 2 * t;
            float bx = bias[col], by = bias[col + 1];
#pragma unroll
            for (int h = 0; h < 2; h++) {
                int row = row0 + h * 8;
                float vx = acc[mi][ni][h * 2 + 0] + bx;
                float vy = acc[mi][ni][h * 2 + 1] + by;
                if (MODE == 0) {
                    *(float2*)&((float*)Cv)[(size_t)row * DM + col] = make_float2(vx, vy);
                } else {
                    int b = row >> 11, s = row & 2047;
                    int hh = col >> 6, e = col & 63;
                    *(uint2*)&((uint32_t*)Cv)[(((size_t)(b * NH + hh)) * SEQ + s) * DEP + e]
                        = make_uint2(f2tf(vx), f2tf(vy));
                }
            }
        }
    }
}

// Fused QKV: blockIdx.z selects projection
__global__ __launch_bounds__(256, 2) void gemm_qkv(
    const uint32_t* __restrict__ x,
    const uint32_t* __restrict__ Wq, const uint32_t* __restrict__ Wk, const uint32_t* __restrict__ Wv,
    const float* __restrict__ bq, const float* __restrict__ bk, const float* __restrict__ bv,
    uint32_t* __restrict__ qo, uint32_t* __restrict__ ko, uint32_t* __restrict__ vo)
{
    int z = blockIdx.z;
    const uint32_t* W = (z == 0) ? Wq : (z == 1) ? Wk : Wv;
    const float*    b = (z == 0) ? bq : (z == 1) ? bk : bv;
    uint32_t*       C = (z == 0) ? qo : (z == 1) ? ko : vo;
    gemm_body<1>(x, W, b, C);
}

__global__ __launch_bounds__(256, 2) void gemm_out(
    const uint32_t* __restrict__ A, const uint32_t* __restrict__ W,
    const float* __restrict__ bias, float* __restrict__ C)
{
    gemm_body<0>(A, W, bias, C);
}

// ---------------------------------------------------------------------------
// Tensor-core flash attention. q/k/v hold tf32 bits; K/V tiles fill via raw
// cp.async (no conversion). Block = 128 threads (4 warps), warp owns 32 rows.
// ---------------------------------------------------------------------------
#define Q_ST 68
#define V_ST 72
#define QROWS 128
#define OFF_Q 0
#define OFF_K (QROWS * Q_ST)
#define OFF_P (OFF_K + 64 * Q_ST)
#define OFF_V (OFF_P + QROWS * Q_ST)
#define ATT_SMEM_WORDS (OFF_V + 64 * V_ST)  /* 26368 -> 105472 B */

__global__ __launch_bounds__(128) void attn_tc(
    const uint32_t* __restrict__ q, const uint32_t* __restrict__ k,
    const uint32_t* __restrict__ v, uint32_t* __restrict__ multi)
{
    extern __shared__ uint32_t sm[];
    uint32_t* Qs = sm + OFF_Q;
    uint32_t* Ks = sm + OFF_K;
    uint32_t* Ps = sm + OFF_P;
    uint32_t* Vs = sm + OFF_V;

    const int tid  = threadIdx.x;
    const int warp = tid >> 5;
    const int lane = tid & 31;
    const int g    = lane >> 2;
    const int t    = lane & 3;
    const int bh   = blockIdx.y;
    const int qt   = blockIdx.x;
    const int mb[2] = { warp * 32, warp * 32 + 16 };

    // ---- load Q 128x64: already tf32-rounded; scale by 1/8 (exact pow2) ----
    {
        const float* qp = (const float*)(q + ((size_t)bh * SEQ + qt * QROWS) * DEP);
#pragma unroll
        for (int p = 0; p < 16; p++) {
            int f4  = p * 128 + tid;
            int row = f4 >> 4;
            int c4  = (f4 & 15) << 2;
            float4 vv = *(const float4*)(qp + (size_t)row * DEP + c4);
            uint32_t* dst = &Qs[row * Q_ST + c4];
            dst[0] = __float_as_uint(vv.x * 0.125f);
            dst[1] = __float_as_uint(vv.y * 0.125f);
            dst[2] = __float_as_uint(vv.z * 0.125f);
            dst[3] = __float_as_uint(vv.w * 0.125f);
        }
    }

    float mr[2][2], l[2][2];
    float O[2][8][4];
#pragma unroll
    for (int mi = 0; mi < 2; mi++) {
        mr[mi][0] = mr[mi][1] = -1e30f;
        l[mi][0] = l[mi][1] = 0.f;
#pragma unroll
        for (int dt = 0; dt < 8; dt++)
#pragma unroll
            for (int r = 0; r < 4; r++) O[mi][dt][r] = 0.f;
    }

    const uint32_t* kbase = k + (size_t)bh * SEQ * DEP;
    const uint32_t* vbase = v + (size_t)bh * SEQ * DEP;

#pragma unroll 1
    for (int t0 = 0; t0 < SEQ; t0 += 64) {
        __syncthreads();   // prev-tile reads done before overwrite
        // ---- K/V tile fill: raw 16B cp.async copies ----
#pragma unroll
        for (int p = 0; p < 8; p++) {
            int f4  = p * 128 + tid;
            int row = f4 >> 4;
            int c4  = (f4 & 15) << 2;
            CP16(smem_u32(&Ks[row * Q_ST + c4]), kbase + (size_t)(t0 + row) * DEP + c4);
            CP16(smem_u32(&Vs[row * V_ST + c4]), vbase + (size_t)(t0 + row) * DEP + c4);
        }
        CP_COMMIT();
        CP_WAIT0();
        __syncthreads();

        // ---- S = Q K^T : 2 m-tiles share every K fragment ----
        float s[2][8][4];
#pragma unroll
        for (int mi = 0; mi < 2; mi++)
#pragma unroll
            for (int nt = 0; nt < 8; nt++)
#pragma unroll
                for (int r = 0; r < 4; r++) s[mi][nt][r] = 0.f;

#pragma unroll
        for (int kk = 0; kk < 8; kk++) {
            const int kb = kk * 8;
            uint32_t a[2][4];
#pragma unroll
            for (int mi = 0; mi < 2; mi++) {
                a[mi][0] = Qs[(mb[mi] + g)     * Q_ST + kb + t];
                a[mi][1] = Qs[(mb[mi] + g + 8) * Q_ST + kb + t];
                a[mi][2] = Qs[(mb[mi] + g)     * Q_ST + kb + t + 4];
                a[mi][3] = Qs[(mb[mi] + g + 8) * Q_ST + kb + t + 4];
            }
#pragma unroll
            for (int nt = 0; nt < 8; nt++) {
                uint32_t b0 = Ks[(nt * 8 + g) * Q_ST + kb + t];
                uint32_t b1 = Ks[(nt * 8 + g) * Q_ST + kb + t + 4];
                mma8(s[0][nt], a[0][0], a[0][1], a[0][2], a[0][3], b0, b1);
                mma8(s[1][nt], a[1][0], a[1][1], a[1][2], a[1][3], b0, b1);
            }
        }

        // ---- online softmax + P write, per m-tile ----
#pragma unroll
        for (int mi = 0; mi < 2; mi++) {
            float mx0 = -1e30f, mx1 = -1e30f;
#pragma unroll
            for (int nt = 0; nt < 8; nt++) {
                mx0 = fmaxf(mx0, fmaxf(s[mi][nt][0], s[mi][nt][1]));
                mx1 = fmaxf(mx1, fmaxf(s[mi][nt][2], s[mi][nt][3]));
            }
            mx0 = fmaxf(mx0, __shfl_xor_sync(0xffffffffu, mx0, 1));
            mx0 = fmaxf(mx0, __shfl_xor_sync(0xffffffffu, mx0, 2));
            mx1 = fmaxf(mx1, __shfl_xor_sync(0xffffffffu, mx1, 1));
            mx1 = fmaxf(mx1, __shfl_xor_sync(0xffffffffu, mx1, 2));

            float mn0 = fmaxf(mr[mi][0], mx0);
            float mn1 = fmaxf(mr[mi][1], mx1);
            float corr0 = __expf(mr[mi][0] - mn0);
            float corr1 = __expf(mr[mi][1] - mn1);

            float sum0 = 0.f, sum1 = 0.f;
#pragma unroll
            for (int nt = 0; nt < 8; nt++) {
                s[mi][nt][0] = __expf(s[mi][nt][0] - mn0);
                s[mi][nt][1] = __expf(s[mi][nt][1] - mn0);
                s[mi][nt][2] = __expf(s[mi][nt][2] - mn1);
                s[mi][nt][3] = __expf(s[mi][nt][3] - mn1);
                sum0 += s[mi][nt][0] + s[mi][nt][1];
                sum1 += s[mi][nt][2] + s[mi][nt][3];
            }
            sum0 += __shfl_xor_sync(0xffffffffu, sum0, 1);
            sum0 += __shfl_xor_sync(0xffffffffu, sum0, 2);
            sum1 += __shfl_xor_sync(0xffffffffu, sum1, 1);
            sum1 += __shfl_xor_sync(0xffffffffu, sum1, 2);
            l[mi][0] = l[mi][0] * corr0 + sum0;
            l[mi][1] = l[mi][1] * corr1 + sum1;

#pragma unroll
            for (int dt = 0; dt < 8; dt++) {
                O[mi][dt][0] *= corr0; O[mi][dt][1] *= corr0;
                O[mi][dt][2] *= corr1; O[mi][dt][3] *= corr1;
            }

#pragma unroll
            for (int nt = 0; nt < 8; nt++) {
                uint2 p01 = make_uint2(f2tf(s[mi][nt][0]), f2tf(s[mi][nt][1]));
                uint2 p23 = make_uint2(f2tf(s[mi][nt][2]), f2tf(s[mi][nt][3]));
                *(uint2*)&Ps[(mb[mi] + g)     * Q_ST + nt * 8 + 2 * t] = p01;
                *(uint2*)&Ps[(mb[mi] + g + 8) * Q_ST + nt * 8 + 2 * t] = p23;
            }
            mr[mi][0] = mn0;
            mr[mi][1] = mn1;
        }
        __syncwarp();   // Ps rows are warp-private

        // ---- O += P V : 2 m-tiles share every V fragment ----
#pragma unroll
        for (int kk = 0; kk < 8; kk++) {
            const int kb = kk * 8;
            uint32_t a[2][4];
#pragma unroll
            for (int mi = 0; mi < 2; mi++) {
                a[mi][0] = Ps[(mb[mi] + g)     * Q_ST + kb + t];
                a[mi][1] = Ps[(mb[mi] + g + 8) * Q_ST + kb + t];
                a[mi][2] = Ps[(mb[mi] + g)     * Q_ST + kb + t + 4];
                a[mi][3] = Ps[(mb[mi] + g + 8) * Q_ST + kb + t + 4];
            }
#pragma unroll
            for (int dt = 0; dt < 8; dt++) {
                uint32_t b0 = Vs[(kb + t)     * V_ST + dt * 8 + g];
                uint32_t b1 = Vs[(kb + t + 4) * V_ST + dt * 8 + g];
                mma8(O[0][dt], a[0][0], a[0][1], a[0][2], a[0][3], b0, b1);
                mma8(O[1][dt], a[1][0], a[1][1], a[1][2], a[1][3], b0, b1);
            }
        }
    }

    // ---- normalize + store to multi [B][S][H*64] as tf32 bits ----
    int b = bh >> 4, h = bh & 15;
#pragma unroll
    for (int mi = 0; mi < 2; mi++) {
        float inv0 = 1.f / l[mi][0], inv1 = 1.f / l[mi][1];
        int srow = qt * QROWS + mb[mi] + g;
        uint32_t* op = multi + ((size_t)(b * SEQ) + srow) * DM + h * DEP;
#pragma unroll
        for (int dt = 0; dt < 8; dt++) {
            int col = dt * 8 + 2 * t;
            *(uint2*)(op + col) =
                make_uint2(f2tf(O[mi][dt][0] * inv0), f2tf(O[mi][dt][1] * inv0));
            *(uint2*)(op + 8 * (size_t)DM + col) =
                make_uint2(f2tf(O[mi][dt][2] * inv1), f2tf(O[mi][dt][3] * inv1));
        }
    }
}

// ---------------------------------------------------------------------------
// Launch: convert -> fused QKV GEMM -> attention -> output GEMM.
// ---------------------------------------------------------------------------
extern "C" void kernel_launch(void* const* d_in, const int* in_sizes, int n_in,
                              void* d_out, int out_size)
{
    const float* x  = (const float*)d_in[0];
    const float* Wq = (const float*)d_in[1];
    const float* bq = (const float*)d_in[2];
    const float* Wk = (const float*)d_in[3];
    const float* bk = (const float*)d_in[4];
    const float* Wv = (const float*)d_in[5];
    const float* bv = (const float*)d_in[6];
    const float* Wo = (const float*)d_in[7];
    const float* bo = (const float*)d_in[8];
    float* out = (float*)d_out;

    uint32_t *qb, *kb, *vb, *mb, *xt, *wqt, *wkt, *wvt, *wot;
    cudaGetSymbolAddress((void**)&qb,  g_q);
    cudaGetSymbolAddress((void**)&kb,  g_k);
    cudaGetSymbolAddress((void**)&vb,  g_v);
    cudaGetSymbolAddress((void**)&mb,  g_multi);
    cudaGetSymbolAddress((void**)&xt,  g_xt);
    cudaGetSymbolAddress((void**)&wqt, g_wqt);
    cudaGetSymbolAddress((void**)&wkt, g_wkt);
    cudaGetSymbolAddress((void**)&wvt, g_wvt);
    cudaGetSymbolAddress((void**)&wot, g_wot);

    const int att_smem = ATT_SMEM_WORDS * 4;   // 105472 bytes
    cudaFuncSetAttribute(attn_tc,  cudaFuncAttributeMaxDynamicSharedMemorySize, att_smem);
    cudaFuncSetAttribute(gemm_qkv, cudaFuncAttributeMaxDynamicSharedMemorySize, GEMM_SMEM_BYTES);
    cudaFuncSetAttribute(gemm_out, cudaFuncAttributeMaxDynamicSharedMemorySize, GEMM_SMEM_BYTES);

    // pre-convert operands to tf32 bits
    const int XW4 = (MROWS * DM) / 4;          // 2,097,152
    const int WW4 = (DM * DM) / 4;             // 262,144
    conv_tf32<<<(XW4 + 255) / 256, 256>>>((const float4*)x,  (uint4*)xt,  XW4);
    conv_tf32<<<(WW4 + 255) / 256, 256>>>((const float4*)Wq, (uint4*)wqt, WW4);
    conv_tf32<<<(WW4 + 255) / 256, 256>>>((const float4*)Wk, (uint4*)wkt, WW4);
    conv_tf32<<<(WW4 + 255) / 256, 256>>>((const float4*)Wv, (uint4*)wvt, WW4);
    conv_tf32<<<(WW4 + 255) / 256, 256>>>((const float4*)Wo, (uint4*)wot, WW4);

    dim3 gq(DM / 128, MROWS / 128, 3);   // (8, 64, 3) fused QKV
    gemm_qkv<<<gq, 256, GEMM_SMEM_BYTES>>>(xt, wqt, wkt, wvt, bq, bk, bv, qb, kb, vb);

    dim3 ga(SEQ / QROWS, BHN);           // (16, 64)
    attn_tc<<<ga, 128, att_smem>>>(qb, kb, vb, mb);

    dim3 gg(DM / 128, MROWS / 128);      // (8, 64)
    gemm_out<<<gg, 256, GEMM_SMEM_BYTES>>>(mb, wot, bo, out);
}